// round 11
// baseline (speedup 1.0000x reference)
#include <cuda_runtime.h>
#include <cstdint>

#define D_DIM   128
#define K_CODES 1024
#define BPX     128            // pixels per block
#define BC      128            // codes per chunk
#define NCHUNK  (K_CODES / BC) // 8
#define TPB     512
#define PSTR    132            // padded row stride (words)
#define PLANE   (64 * PSTR)    // words per packed plane (64 k-pairs x 132)
#define XWORDS  (2 * PLANE)    // X hi + X lo planes
#define BBUF    (2 * PLANE)    // per-chunk B buffer: hi + lo planes
#define SMEM_DYN ((XWORDS + 2 * BBUF) * 4)   // 202752 B

// Static scratch (no dynamic allocation allowed)
__device__ float    g_Et[D_DIM * K_CODES];       // transposed codebook (output gather)
__device__ float    g_e2[K_CODES];
__device__ unsigned g_B0[NCHUNK * 64 * BC];      // codebook bf16x2 hi plane  [ch][kp][code]
__device__ unsigned g_B1[NCHUNK * 64 * BC];      // codebook bf16x2 residual plane

// pack: element0 (even k) -> low half, element1 (odd k) -> high half
__device__ __forceinline__ unsigned packbf(float lo, float hi) {
    unsigned r; asm("cvt.rn.bf16x2.f32 %0, %1, %2;" : "=r"(r) : "f"(hi), "f"(lo)); return r;
}
__device__ __forceinline__ float lo_f(unsigned p) { return __uint_as_float(p << 16); }
__device__ __forceinline__ float hi_f(unsigned p) { return __uint_as_float(p & 0xFFFF0000u); }
__device__ __forceinline__ void split2(float e0, float e1, unsigned& pH, unsigned& pL) {
    pH = packbf(e0, e1);
    pL = packbf(__fsub_rn(e0, lo_f(pH)), __fsub_rn(e1, hi_f(pH)));
}
__device__ __forceinline__ void mma16(float* d, const unsigned* a, unsigned b0, unsigned b1) {
    asm volatile(
        "mma.sync.aligned.m16n8k16.row.col.f32.bf16.bf16.f32 "
        "{%0,%1,%2,%3}, {%4,%5,%6,%7}, {%8,%9}, {%0,%1,%2,%3};"
        : "+f"(d[0]), "+f"(d[1]), "+f"(d[2]), "+f"(d[3])
        : "r"(a[0]), "r"(a[1]), "r"(a[2]), "r"(a[3]), "r"(b0), "r"(b1));
}
__device__ __forceinline__ void cp16(void* s, const void* g) {
    unsigned sa = (unsigned)__cvta_generic_to_shared(s);
    asm volatile("cp.async.cg.shared.global [%0], [%1], 16;" :: "r"(sa), "l"(g));
}

// prep: transpose codebook, e2, and packed bf16x2 hi/lo planes per chunk.
__global__ void prep_kernel(const float* __restrict__ cb) {
    int i = blockIdx.x * blockDim.x + threadIdx.x;
    int nt = gridDim.x * blockDim.x;
    for (int idx = i; idx < D_DIM * K_CODES; idx += nt) {
        int k = idx >> 7, d = idx & 127;
        g_Et[d * K_CODES + k] = cb[idx];
    }
    for (int idx = i; idx < K_CODES * 64; idx += nt) {   // (code, k-pair)
        int k = idx >> 6, kp = idx & 63;
        float e0 = cb[k * D_DIM + 2 * kp];
        float e1 = cb[k * D_DIM + 2 * kp + 1];
        unsigned pH, pL;
        split2(e0, e1, pH, pL);
        int ch = k >> 7, c = k & 127;
        g_B0[(ch * 64 + kp) * BC + c] = pH;
        g_B1[(ch * 64 + kp) * BC + c] = pL;
    }
    for (int k = i; k < K_CODES; k += nt) {
        const float* row = cb + k * D_DIM;
        float s = 0.f;
        for (int d = 0; d < D_DIM; d++) s = __fadd_rn(s, __fmul_rn(row[d], row[d]));
        g_e2[k] = s;
    }
}

__global__ __launch_bounds__(TPB, 1) void vq_main(const float* __restrict__ lat,
                                                  float* __restrict__ out) {
    extern __shared__ unsigned smem[];
    unsigned* X0p = smem;                  // [kp][px] packed bf16x2 hi
    unsigned* X1p = smem + PLANE;          // residual
    unsigned* Bbase = smem + XWORDS;       // 2 buffers x (hi plane | lo plane)

    __shared__ float x2s[BPX];
    __shared__ float e2s[K_CODES];
    __shared__ float bVs2[BPX * 4];        // per-(row, n-warp) staging
    __shared__ int   bIs2[BPX * 4];
    __shared__ int   bIs[BPX];

    const int tid  = threadIdx.x;
    const int wid  = tid >> 5;
    const int lane = tid & 31;
    const int g    = lane >> 2;      // fragment row/col group
    const int t4   = lane & 3;       // k-pair selector
    const int w_m  = wid >> 2;       // 4 m-warps
    const int w_n  = wid & 3;        // 4 n-warps
    const int p0   = w_m * 32;       // warp pixel base
    const int c0   = w_n * 32;       // warp code base within chunk

    const int gp  = blockIdx.x * BPX;
    const int b   = gp >> 12;
    const int hw0 = gp & 4095;
    const float* latbase = lat + (size_t)b * D_DIM * 4096 + hw0;

    // Issue chunk-0 B-plane loads (async) first.
    for (int i = tid; i < 2 * 64 * 32; i += TPB) {
        int pl = i >> 11, r = (i >> 5) & 63, s = i & 31;
        const unsigned* src = (pl ? g_B1 : g_B0) + (size_t)r * BC + s * 4;
        cp16(&Bbase[pl * PLANE + r * PSTR + s * 4], src);
    }
    asm volatile("cp.async.commit_group;");

    // Convert X once: packed bf16x2 hi/lo planes [kp][px].
    for (int i = tid; i < 64 * BPX; i += TPB) {
        int kp = i >> 7, px = i & 127;
        float xe = latbase[(size_t)(2 * kp) * 4096 + px];
        float xo = latbase[(size_t)(2 * kp + 1) * 4096 + px];
        unsigned pH, pL;
        split2(xe, xo, pH, pL);
        X0p[kp * PSTR + px] = pH;
        X1p[kp * PSTR + px] = pL;
    }
    for (int i = tid; i < K_CODES; i += TPB) e2s[i] = g_e2[i];

    // x2 per pixel (same sequential-d fp32 sum as the certified kernels)
    if (tid < BPX) {
        float s = 0.f;
        for (int d = 0; d < D_DIM; d++) {
            float v = latbase[(size_t)d * 4096 + tid];
            s = __fadd_rn(s, __fmul_rn(v, v));
        }
        x2s[tid] = s;
    }
    asm volatile("cp.async.wait_group 0;" ::: "memory");
    __syncthreads();

    // Per-thread row slots: slot = m*2+rr -> pixel row p0 + m*16 + rr*8 + g
    float x2r[4], bv[4];
    int   bi[4];
    #pragma unroll
    for (int s = 0; s < 4; s++) {
        x2r[s] = x2s[p0 + (s >> 1) * 16 + (s & 1) * 8 + g];
        bv[s] = 3.4e38f; bi[s] = 0;
    }

    for (int ch = 0; ch < NCHUNK; ch++) {
        unsigned* Bb = Bbase + (ch & 1) * BBUF;

        if (ch + 1 < NCHUNK) {   // prefetch next chunk's planes into other buffer
            unsigned* nb = Bbase + ((ch + 1) & 1) * BBUF;
            for (int i = tid; i < 2 * 64 * 32; i += TPB) {
                int pl = i >> 11, r = (i >> 5) & 63, s = i & 31;
                const unsigned* src = (pl ? g_B1 : g_B0) + (size_t)((ch + 1) * 64 + r) * BC + s * 4;
                cp16(&nb[pl * PLANE + r * PSTR + s * 4], src);
            }
            asm volatile("cp.async.commit_group;");
        }

        float D[2][4][4];
        #pragma unroll
        for (int m = 0; m < 2; m++)
            #pragma unroll
            for (int n = 0; n < 4; n++)
                #pragma unroll
                for (int q = 0; q < 4; q++) D[m][n][q] = 0.f;

        #pragma unroll 2
        for (int kb = 0; kb < 8; kb++) {       // 8 k-blocks of 16
            const int r0 = kb * 8 + t4;        // k-pair rows for this thread
            const int r1 = r0 + 4;
            unsigned aH[2][4], aL[2][4], bH[4][2], bL[4][2];
            #pragma unroll
            for (int m = 0; m < 2; m++) {
                const int pxb = p0 + m * 16 + g;
                aH[m][0] = X0p[r0 * PSTR + pxb];
                aH[m][1] = X0p[r0 * PSTR + pxb + 8];
                aH[m][2] = X0p[r1 * PSTR + pxb];
                aH[m][3] = X0p[r1 * PSTR + pxb + 8];
                aL[m][0] = X1p[r0 * PSTR + pxb];
                aL[m][1] = X1p[r0 * PSTR + pxb + 8];
                aL[m][2] = X1p[r1 * PSTR + pxb];
                aL[m][3] = X1p[r1 * PSTR + pxb + 8];
            }
            #pragma unroll
            for (int n = 0; n < 4; n++) {
                const int cc = c0 + n * 8 + g;
                bH[n][0] = Bb[r0 * PSTR + cc];
                bH[n][1] = Bb[r1 * PSTR + cc];
                bL[n][0] = Bb[PLANE + r0 * PSTR + cc];
                bL[n][1] = Bb[PLANE + r1 * PSTR + cc];
            }
            // pass-major: 8 independent accumulator chains per pass
            #pragma unroll
            for (int n = 0; n < 4; n++)
                #pragma unroll
                for (int m = 0; m < 2; m++) mma16(D[m][n], aH[m], bH[n][0], bH[n][1]);
            #pragma unroll
            for (int n = 0; n < 4; n++)
                #pragma unroll
                for (int m = 0; m < 2; m++) mma16(D[m][n], aL[m], bH[n][0], bH[n][1]);
            #pragma unroll
            for (int n = 0; n < 4; n++)
                #pragma unroll
                for (int m = 0; m < 2; m++) mma16(D[m][n], aH[m], bL[n][0], bL[n][1]);
        }

        // ---- epilogue: exact reference score formula, running first-min argmin ----
        const int cg0 = ch * BC + c0;
        #pragma unroll
        for (int m = 0; m < 2; m++) {
            #pragma unroll
            for (int rr = 0; rr < 2; rr++) {
                const int slot = m * 2 + rr;
                const float x2 = x2r[slot];
                float v = bv[slot]; int idx = bi[slot];
                #pragma unroll
                for (int n = 0; n < 4; n++) {
                    const int cbase = cg0 + n * 8 + 2 * t4;
                    float2 e2p = *(const float2*)&e2s[cbase];
                    float d0 = D[m][n][rr * 2 + 0];
                    float d1 = D[m][n][rr * 2 + 1];
                    // d2 = fl(fl(x2 - 2*dot) + e2) — replicates reference fp32 formula
                    float s0 = __fadd_rn(__fsub_rn(x2, __fmul_rn(2.0f, d0)), e2p.x);
                    float s1 = __fadd_rn(__fsub_rn(x2, __fmul_rn(2.0f, d1)), e2p.y);
                    if (s0 < v) { v = s0; idx = cbase; }
                    if (s1 < v) { v = s1; idx = cbase + 1; }
                }
                bv[slot] = v; bi[slot] = idx;
            }
        }

        if (ch + 1 < NCHUNK)
            asm volatile("cp.async.wait_group 0;" ::: "memory");
        __syncthreads();
    }

    // Reduce within quad (lanes sharing a pixel row), ties -> lower index.
    #pragma unroll
    for (int s = 0; s < 4; s++) {
        float v = bv[s]; int idx = bi[s];
        #pragma unroll
        for (int off = 1; off < 4; off <<= 1) {
            float ov = __shfl_xor_sync(0xffffffffu, v, off);
            int   oi = __shfl_xor_sync(0xffffffffu, idx, off);
            if (ov < v || (ov == v && oi < idx)) { v = ov; idx = oi; }
        }
        bv[s] = v; bi[s] = idx;
    }
    // Stage per-(row, n-warp) results, then merge with explicit index tie-break
    // (warps' code sets interleave across chunks, so ascending w_n is NOT
    // ascending global index — must compare indices on exact ties).
    if (t4 == 0) {
        #pragma unroll
        for (int s = 0; s < 4; s++) {
            int row = p0 + (s >> 1) * 16 + (s & 1) * 8 + g;
            bVs2[row * 4 + w_n] = bv[s];
            bIs2[row * 4 + w_n] = bi[s];
        }
    }
    __syncthreads();
    if (tid < BPX) {
        float v = bVs2[tid * 4]; int idx = bIs2[tid * 4];
        #pragma unroll
        for (int j = 1; j < 4; j++) {
            float ov = bVs2[tid * 4 + j]; int oi = bIs2[tid * 4 + j];
            if (ov < v || (ov == v && oi < idx)) { v = ov; idx = oi; }
        }
        bIs[tid] = idx;
    }
    __syncthreads();

    // Gather codebook rows and write channel-first output (coalesced stores).
    float* outbase = out + (size_t)b * D_DIM * 4096 + hw0;
    for (int i = tid; i < D_DIM * BPX; i += TPB) {
        int d = i >> 7, px = i & 127;
        outbase[(size_t)d * 4096 + px] = __ldg(&g_Et[d * K_CODES + bIs[px]]);
    }
}

extern "C" void kernel_launch(void* const* d_in, const int* in_sizes, int n_in,
                              void* d_out, int out_size) {
    const float* lat = (const float*)d_in[0];
    const float* cb  = (const float*)d_in[1];
    float* out = (float*)d_out;
    cudaFuncSetAttribute(vq_main, cudaFuncAttributeMaxDynamicSharedMemorySize, SMEM_DYN);
    prep_kernel<<<128, 256>>>(cb);
    vq_main<<<512, TPB, SMEM_DYN>>>(lat, out);
}

// round 12
// speedup vs baseline: 1.1900x; 1.1900x over previous
#include <cuda_runtime.h>
#include <cstdint>

#define D_DIM   128
#define K_CODES 1024
#define BPX     128            // pixels per block
#define BC      128            // codes per chunk
#define NCHUNK  (K_CODES / BC) // 8
#define TPB     256
#define PSTR    136            // padded row stride (words), 136 % 32 == 8 -> conflict-free frags
#define PLANE   (64 * PSTR)    // words per packed plane (64 k-pairs x 136)
#define XWORDS  (2 * PLANE)    // X hi + X lo planes
#define BBUF    (2 * PLANE)    // per-chunk B buffer: hi + lo planes
#define SMEM_DYN ((XWORDS + 2 * BBUF) * 4)   // 208896 B

// Static scratch (no dynamic allocation allowed)
__device__ float    g_Et[D_DIM * K_CODES];       // transposed codebook (output gather)
__device__ float    g_e2[K_CODES];
__device__ unsigned g_B0[NCHUNK * 64 * BC];      // codebook bf16x2 hi plane  [ch][kp][code]
__device__ unsigned g_B1[NCHUNK * 64 * BC];      // codebook bf16x2 residual plane

// pack: element0 (even k) -> low half, element1 (odd k) -> high half
__device__ __forceinline__ unsigned packbf(float lo, float hi) {
    unsigned r; asm("cvt.rn.bf16x2.f32 %0, %1, %2;" : "=r"(r) : "f"(hi), "f"(lo)); return r;
}
__device__ __forceinline__ float lo_f(unsigned p) { return __uint_as_float(p << 16); }
__device__ __forceinline__ float hi_f(unsigned p) { return __uint_as_float(p & 0xFFFF0000u); }
__device__ __forceinline__ void split2(float e0, float e1, unsigned& pH, unsigned& pL) {
    pH = packbf(e0, e1);
    pL = packbf(__fsub_rn(e0, lo_f(pH)), __fsub_rn(e1, hi_f(pH)));
}
__device__ __forceinline__ void mma16(float* d, const unsigned* a, unsigned b0, unsigned b1) {
    asm volatile(
        "mma.sync.aligned.m16n8k16.row.col.f32.bf16.bf16.f32 "
        "{%0,%1,%2,%3}, {%4,%5,%6,%7}, {%8,%9}, {%0,%1,%2,%3};"
        : "+f"(d[0]), "+f"(d[1]), "+f"(d[2]), "+f"(d[3])
        : "r"(a[0]), "r"(a[1]), "r"(a[2]), "r"(a[3]), "r"(b0), "r"(b1));
}
__device__ __forceinline__ void cp16(void* s, const void* g) {
    unsigned sa = (unsigned)__cvta_generic_to_shared(s);
    asm volatile("cp.async.cg.shared.global [%0], [%1], 16;" :: "r"(sa), "l"(g));
}

// prep: transpose codebook, e2, and packed bf16x2 hi/lo planes per chunk.
__global__ void prep_kernel(const float* __restrict__ cb) {
    int i = blockIdx.x * blockDim.x + threadIdx.x;
    int nt = gridDim.x * blockDim.x;
    for (int idx = i; idx < D_DIM * K_CODES; idx += nt) {
        int k = idx >> 7, d = idx & 127;
        g_Et[d * K_CODES + k] = cb[idx];
    }
    for (int idx = i; idx < K_CODES * 64; idx += nt) {   // (code, k-pair)
        int k = idx >> 6, kp = idx & 63;
        float e0 = cb[k * D_DIM + 2 * kp];
        float e1 = cb[k * D_DIM + 2 * kp + 1];
        unsigned pH, pL;
        split2(e0, e1, pH, pL);
        int ch = k >> 7, c = k & 127;
        g_B0[(ch * 64 + kp) * BC + c] = pH;
        g_B1[(ch * 64 + kp) * BC + c] = pL;
    }
    for (int k = i; k < K_CODES; k += nt) {
        const float* row = cb + k * D_DIM;
        float s = 0.f;
        for (int d = 0; d < D_DIM; d++) s = __fadd_rn(s, __fmul_rn(row[d], row[d]));
        g_e2[k] = s;
    }
}

__global__ __launch_bounds__(TPB, 1) void vq_main(const float* __restrict__ lat,
                                                  float* __restrict__ out) {
    extern __shared__ unsigned smem[];
    unsigned* X0p = smem;                  // [kp][px] packed bf16x2 hi
    unsigned* X1p = smem + PLANE;          // residual
    unsigned* Bbase = smem + XWORDS;       // 2 buffers x (hi plane | lo plane)

    __shared__ float x2s[BPX];
    __shared__ float e2s[K_CODES];
    __shared__ float bVs[BPX];
    __shared__ int   bIs[BPX];

    const int tid  = threadIdx.x;
    const int wid  = tid >> 5;
    const int lane = tid & 31;
    const int g    = lane >> 2;      // fragment row/col group
    const int t4   = lane & 3;       // k-pair selector
    const int w_m  = wid >> 1;       // 4 m-warps
    const int w_n  = wid & 1;        // 2 n-warps
    const int p0   = w_m * 32;       // warp pixel base
    const int c0   = w_n * 64;       // warp code base within chunk

    const int gp  = blockIdx.x * BPX;
    const int b   = gp >> 12;
    const int hw0 = gp & 4095;
    const float* latbase = lat + (size_t)b * D_DIM * 4096 + hw0;

    // Issue chunk-0 B-plane loads (async) first.
    for (int i = tid; i < 2 * 64 * 32; i += TPB) {
        int pl = i >> 11, r = (i >> 5) & 63, s = i & 31;
        const unsigned* src = (pl ? g_B1 : g_B0) + (size_t)r * BC + s * 4;
        cp16(&Bbase[pl * PLANE + r * PSTR + s * 4], src);
    }
    asm volatile("cp.async.commit_group;");

    // Convert X once: packed bf16x2 hi/lo planes [kp][px].
    for (int i = tid; i < 64 * BPX; i += TPB) {
        int kp = i >> 7, px = i & 127;
        float xe = latbase[(size_t)(2 * kp) * 4096 + px];
        float xo = latbase[(size_t)(2 * kp + 1) * 4096 + px];
        unsigned pH, pL;
        split2(xe, xo, pH, pL);
        X0p[kp * PSTR + px] = pH;
        X1p[kp * PSTR + px] = pL;
    }
    for (int i = tid; i < K_CODES; i += TPB) e2s[i] = g_e2[i];

    // x2 per pixel (same sequential-d fp32 sum as the certified kernels)
    if (tid < BPX) {
        float s = 0.f;
        for (int d = 0; d < D_DIM; d++) {
            float v = latbase[(size_t)d * 4096 + tid];
            s = __fadd_rn(s, __fmul_rn(v, v));
        }
        x2s[tid] = s;
    }
    asm volatile("cp.async.wait_group 0;" ::: "memory");
    __syncthreads();

    // Per-thread row slots: slot = m*2+rr -> pixel row p0 + m*16 + rr*8 + g
    float x2r[4], bv[4];
    int   bi[4];
    #pragma unroll
    for (int s = 0; s < 4; s++) {
        x2r[s] = x2s[p0 + (s >> 1) * 16 + (s & 1) * 8 + g];
        bv[s] = 3.4e38f; bi[s] = 0;
    }

    for (int ch = 0; ch < NCHUNK; ch++) {
        unsigned* Bb = Bbase + (ch & 1) * BBUF;

        if (ch + 1 < NCHUNK) {   // prefetch next chunk's planes into other buffer
            unsigned* nb = Bbase + ((ch + 1) & 1) * BBUF;
            for (int i = tid; i < 2 * 64 * 32; i += TPB) {
                int pl = i >> 11, r = (i >> 5) & 63, s = i & 31;
                const unsigned* src = (pl ? g_B1 : g_B0) + (size_t)((ch + 1) * 64 + r) * BC + s * 4;
                cp16(&nb[pl * PLANE + r * PSTR + s * 4], src);
            }
            asm volatile("cp.async.commit_group;");
        }

        float D[2][8][4];
        #pragma unroll
        for (int m = 0; m < 2; m++)
            #pragma unroll
            for (int n = 0; n < 8; n++)
                #pragma unroll
                for (int q = 0; q < 4; q++) D[m][n][q] = 0.f;

        #pragma unroll 2
        for (int kb = 0; kb < 8; kb++) {       // 8 k-blocks of 16
            const int r0 = kb * 8 + t4;        // k-pair rows for this thread
            const int r1 = r0 + 4;
            unsigned aH[2][4], aL[2][4], bH[8][2], bL[8][2];
            #pragma unroll
            for (int m = 0; m < 2; m++) {
                const int pxb = p0 + m * 16 + g;
                aH[m][0] = X0p[r0 * PSTR + pxb];
                aH[m][1] = X0p[r0 * PSTR + pxb + 8];
                aH[m][2] = X0p[r1 * PSTR + pxb];
                aH[m][3] = X0p[r1 * PSTR + pxb + 8];
                aL[m][0] = X1p[r0 * PSTR + pxb];
                aL[m][1] = X1p[r0 * PSTR + pxb + 8];
                aL[m][2] = X1p[r1 * PSTR + pxb];
                aL[m][3] = X1p[r1 * PSTR + pxb + 8];
            }
            #pragma unroll
            for (int n = 0; n < 8; n++) {
                const int cc = c0 + n * 8 + g;
                bH[n][0] = Bb[r0 * PSTR + cc];
                bH[n][1] = Bb[r1 * PSTR + cc];
                bL[n][0] = Bb[PLANE + r0 * PSTR + cc];
                bL[n][1] = Bb[PLANE + r1 * PSTR + cc];
            }
            // pass-major: 16 independent accumulator chains per pass
            #pragma unroll
            for (int n = 0; n < 8; n++)
                #pragma unroll
                for (int m = 0; m < 2; m++) mma16(D[m][n], aH[m], bH[n][0], bH[n][1]);
            #pragma unroll
            for (int n = 0; n < 8; n++)
                #pragma unroll
                for (int m = 0; m < 2; m++) mma16(D[m][n], aL[m], bH[n][0], bH[n][1]);
            #pragma unroll
            for (int n = 0; n < 8; n++)
                #pragma unroll
                for (int m = 0; m < 2; m++) mma16(D[m][n], aH[m], bL[n][0], bL[n][1]);
        }

        // ---- epilogue: exact reference score formula, running first-min argmin ----
        const int cg0 = ch * BC + c0;
        #pragma unroll
        for (int m = 0; m < 2; m++) {
            #pragma unroll
            for (int rr = 0; rr < 2; rr++) {
                const int slot = m * 2 + rr;
                const float x2 = x2r[slot];
                float v = bv[slot]; int idx = bi[slot];
                #pragma unroll
                for (int n = 0; n < 8; n++) {
                    const int cbase = cg0 + n * 8 + 2 * t4;
                    float2 e2p = *(const float2*)&e2s[cbase];
                    float d0 = D[m][n][rr * 2 + 0];
                    float d1 = D[m][n][rr * 2 + 1];
                    // d2 = fl(fl(x2 - 2*dot) + e2) — replicates reference fp32 formula
                    float s0 = __fadd_rn(__fsub_rn(x2, __fmul_rn(2.0f, d0)), e2p.x);
                    float s1 = __fadd_rn(__fsub_rn(x2, __fmul_rn(2.0f, d1)), e2p.y);
                    if (s0 < v) { v = s0; idx = cbase; }
                    if (s1 < v) { v = s1; idx = cbase + 1; }
                }
                bv[slot] = v; bi[slot] = idx;
            }
        }

        if (ch + 1 < NCHUNK)
            asm volatile("cp.async.wait_group 0;" ::: "memory");
        __syncthreads();
    }

    // Reduce within quad (lanes sharing a pixel row), ties -> lower index.
    #pragma unroll
    for (int s = 0; s < 4; s++) {
        float v = bv[s]; int idx = bi[s];
        #pragma unroll
        for (int off = 1; off < 4; off <<= 1) {
            float ov = __shfl_xor_sync(0xffffffffu, v, off);
            int   oi = __shfl_xor_sync(0xffffffffu, idx, off);
            if (ov < v || (ov == v && oi < idx)) { v = ov; idx = oi; }
        }
        bv[s] = v; bi[s] = idx;
    }
    // Merge the two n-warps per pixel row (explicit index tie-break).
    if (w_n == 0 && t4 == 0) {
        #pragma unroll
        for (int s = 0; s < 4; s++) {
            int row = p0 + (s >> 1) * 16 + (s & 1) * 8 + g;
            bVs[row] = bv[s]; bIs[row] = bi[s];
        }
    }
    __syncthreads();
    if (w_n == 1 && t4 == 0) {
        #pragma unroll
        for (int s = 0; s < 4; s++) {
            int row = p0 + (s >> 1) * 16 + (s & 1) * 8 + g;
            if (bv[s] < bVs[row] || (bv[s] == bVs[row] && bi[s] < bIs[row])) {
                bVs[row] = bv[s]; bIs[row] = bi[s];
            }
        }
    }
    __syncthreads();

    // Gather codebook rows and write channel-first output (coalesced stores).
    float* outbase = out + (size_t)b * D_DIM * 4096 + hw0;
    for (int i = tid; i < D_DIM * BPX; i += TPB) {
        int d = i >> 7, px = i & 127;
        outbase[(size_t)d * 4096 + px] = __ldg(&g_Et[d * K_CODES + bIs[px]]);
    }
}

extern "C" void kernel_launch(void* const* d_in, const int* in_sizes, int n_in,
                              void* d_out, int out_size) {
    const float* lat = (const float*)d_in[0];
    const float* cb  = (const float*)d_in[1];
    float* out = (float*)d_out;
    cudaFuncSetAttribute(vq_main, cudaFuncAttributeMaxDynamicSharedMemorySize, SMEM_DYN);
    prep_kernel<<<128, 256>>>(cb);
    vq_main<<<512, TPB, SMEM_DYN>>>(lat, out);
}